// round 6
// baseline (speedup 1.0000x reference)
#include <cuda_runtime.h>
#include <math.h>

// ---------------- problem constants ----------------
#define BATCH   32
#define NCLS    60
#define BNC     1920          // BATCH*NCLS
#define DD      256
#define SS      72
#define NH      8
#define HDIM    32
#define TOPM    20
#define NLAYERS 2
#define MTOT    (BNC*SS)      // 138240 rows
#define LN_EPS  1e-5f

// ---------------- scratch (device globals; no cudaMalloc allowed) ----------------
__device__ float g_x  [(size_t)MTOT*DD];      // current activations (B,S,D)
__device__ float g_qkv[(size_t)MTOT*3*DD];    // qkv projections
__device__ float g_att[(size_t)MTOT*DD];      // attention output
__device__ float g_tmp[(size_t)MTOT*DD];      // proj + residual (pre-LN)

// ---------------- tf32 helpers ----------------
__device__ __forceinline__ unsigned f2tf32(float f) {
    unsigned r;
    asm("cvt.rna.tf32.f32 %0, %1;" : "=r"(r) : "f"(f));
    return r;
}
// split x into hi (tf32) + lo (tf32 of remainder): hi+lo carries ~22 mantissa bits
__device__ __forceinline__ void split_tf32(float v, unsigned& hi, unsigned& lo) {
    hi = f2tf32(v);
    lo = f2tf32(v - __uint_as_float(hi));
}

__device__ __forceinline__ void mma_tf32(float* c, const unsigned* a, const unsigned* b) {
    asm volatile(
        "mma.sync.aligned.m16n8k8.row.col.f32.tf32.tf32.f32 "
        "{%0,%1,%2,%3}, {%4,%5,%6,%7}, {%8,%9}, {%0,%1,%2,%3};"
        : "+f"(c[0]), "+f"(c[1]), "+f"(c[2]), "+f"(c[3])
        : "r"(a[0]), "r"(a[1]), "r"(a[2]), "r"(a[3]),
          "r"(b[0]), "r"(b[1]));
}

// ---------------- cp.async helpers ----------------
__device__ __forceinline__ void cp_async16(void* smem, const void* gmem) {
    unsigned s = (unsigned)__cvta_generic_to_shared(smem);
    asm volatile("cp.async.cg.shared.global [%0], [%1], 16;\n" :: "r"(s), "l"(gmem));
}
__device__ __forceinline__ void cp_commit() { asm volatile("cp.async.commit_group;\n"); }
__device__ __forceinline__ void cp_wait1()  { asm volatile("cp.async.wait_group 1;\n"); }
__device__ __forceinline__ void cp_wait0()  { asm volatile("cp.async.wait_group 0;\n"); }

// ---------------- kernel 1: transpose (BNC,D,S)->(BNC,S,D) + pos embed ----------------
__global__ __launch_bounds__(256) void k_transpose(const float* __restrict__ f,
                                                   const float* __restrict__ pos,
                                                   float* __restrict__ x) {
    __shared__ float t[32][33];
    int b  = blockIdx.x;
    int s0 = blockIdx.y * 32;
    int d0 = blockIdx.z * 32;
    int tx = threadIdx.x, ty = threadIdx.y;       // block (32,8)
    const float* fb = f + (size_t)b * DD * SS;
    #pragma unroll
    for (int i = 0; i < 4; i++) {
        int d = d0 + ty + i*8;
        int s = s0 + tx;
        t[ty + i*8][tx] = (s < SS) ? fb[d * SS + s] : 0.f;
    }
    __syncthreads();
    float* xb = x + (size_t)b * SS * DD;
    #pragma unroll
    for (int i = 0; i < 4; i++) {
        int s = s0 + ty + i*8;
        int d = d0 + tx;
        if (s < SS) xb[s * DD + d] = t[tx][ty + i*8] + pos[s * DD + d];
    }
}

// ---------------- kernel 2: 3xTF32 tensor-core GEMM, 2-stage cp.async pipeline ----------
// C[M,N] = A[M,256] @ B[256,N] + bias (+res).  Block tile 128x64, 8 warps (4m x 2n),
// warp 32x32 via m16n8k8. Each operand split hi/lo in registers -> 3 mmas (near-fp32).
__global__ __launch_bounds__(256, 2) void k_gemm_tf32x3(const float* __restrict__ A,
                                                        const float* __restrict__ B,
                                                        const float* __restrict__ bias,
                                                        const float* __restrict__ res,
                                                        float* __restrict__ C, int N) {
    __shared__ __align__(16) float As[2][128][36];
    __shared__ __align__(16) float Bs[2][32][72];
    const int tid  = threadIdx.x;
    const int m0   = blockIdx.y * 128;
    const int n0   = blockIdx.x * 64;
    const int warp = tid >> 5, lane = tid & 31;
    const int wm   = warp & 3;    // m offset 32*wm
    const int wn   = warp >> 2;   // n offset 32*wn
    const int g    = lane >> 2;   // 0..7
    const int t    = lane & 3;    // 0..3

    float acc[2][4][4];
    #pragma unroll
    for (int i = 0; i < 2; i++)
        #pragma unroll
        for (int j = 0; j < 4; j++)
            #pragma unroll
            for (int r = 0; r < 4; r++) acc[i][j][r] = 0.f;

    // stage loader: A tile 128x32 (4 x cp16/thread), B tile 32x64 (2 x cp16/thread)
    auto load_stage = [&](int st, int k0) {
        #pragma unroll
        for (int i = 0; i < 4; i++) {
            int idx = tid + i * 256;
            int m = idx >> 3, kc = idx & 7;
            cp_async16(&As[st][m][kc * 4], A + (size_t)(m0 + m) * 256 + k0 + kc * 4);
        }
        #pragma unroll
        for (int i = 0; i < 2; i++) {
            int idx = tid + i * 256;
            int k = idx >> 4, nc = idx & 15;
            cp_async16(&Bs[st][k][nc * 4], B + (size_t)(k0 + k) * N + n0 + nc * 4);
        }
        cp_commit();
    };

    load_stage(0, 0);
    #pragma unroll
    for (int kc = 0; kc < 8; kc++) {
        const int st = kc & 1;
        if (kc < 7) load_stage(st ^ 1, (kc + 1) * 32);
        if (kc < 7) cp_wait1(); else cp_wait0();
        __syncthreads();
        #pragma unroll
        for (int ks = 0; ks < 4; ks++) {
            unsigned ah[2][4], al[2][4], bh[4][2], bl[4][2];
            #pragma unroll
            for (int mt = 0; mt < 2; mt++) {
                int mr = wm * 32 + mt * 16;
                split_tf32(As[st][mr + g    ][ks * 8 + t    ], ah[mt][0], al[mt][0]);
                split_tf32(As[st][mr + g + 8][ks * 8 + t    ], ah[mt][1], al[mt][1]);
                split_tf32(As[st][mr + g    ][ks * 8 + t + 4], ah[mt][2], al[mt][2]);
                split_tf32(As[st][mr + g + 8][ks * 8 + t + 4], ah[mt][3], al[mt][3]);
            }
            #pragma unroll
            for (int nt = 0; nt < 4; nt++) {
                int nc = wn * 32 + nt * 8;
                split_tf32(Bs[st][ks * 8 + t    ][nc + g], bh[nt][0], bl[nt][0]);
                split_tf32(Bs[st][ks * 8 + t + 4][nc + g], bh[nt][1], bl[nt][1]);
            }
            #pragma unroll
            for (int mt = 0; mt < 2; mt++)
                #pragma unroll
                for (int nt = 0; nt < 4; nt++) {
                    mma_tf32(acc[mt][nt], ah[mt], bl[nt]);   // cross terms first
                    mma_tf32(acc[mt][nt], al[mt], bh[nt]);
                    mma_tf32(acc[mt][nt], ah[mt], bh[nt]);   // dominant term
                }
        }
        __syncthreads();
    }
    // epilogue: bias (+residual), float2 stores
    #pragma unroll
    for (int mt = 0; mt < 2; mt++) {
        #pragma unroll
        for (int nt = 0; nt < 4; nt++) {
            int m = m0 + wm * 32 + mt * 16 + g;
            int n = n0 + wn * 32 + nt * 8 + 2 * t;
            float bx = bias[n], by = bias[n + 1];
            float2 o0 = make_float2(acc[mt][nt][0] + bx, acc[mt][nt][1] + by);
            float2 o1 = make_float2(acc[mt][nt][2] + bx, acc[mt][nt][3] + by);
            if (res) {
                float2 r0 = *(const float2*)(res + (size_t)m * N + n);
                float2 r1 = *(const float2*)(res + (size_t)(m + 8) * N + n);
                o0.x += r0.x; o0.y += r0.y;
                o1.x += r1.x; o1.y += r1.y;
            }
            *(float2*)(C + (size_t)m * N + n)       = o0;
            *(float2*)(C + (size_t)(m + 8) * N + n) = o1;
        }
    }
}

// ---------------- kernel 3: top-M attention per (batch, head) ----------------
// smem tiles padded to 80 rows (zero-filled) -> no index clamps anywhere.
__global__ __launch_bounds__(256) void k_attn(const float* __restrict__ qkv,
                                              float* __restrict__ out) {
    __shared__ float sq[80][33];   // q, later reused for v (rows 72..79 stay zero)
    __shared__ float sk[80][33];
    __shared__ float sc[80][81];   // scores -> probs
    const int b = blockIdx.x;
    const int h = blockIdx.y;
    const int tid = threadIdx.x;
    const float* base = qkv + (size_t)b * SS * 768 + h * HDIM;
    // load q, k (zero-pad rows 72..79)
    for (int idx = tid; idx < 80 * HDIM; idx += 256) {
        int s_ = idx >> 5, d = idx & 31;
        bool ok = s_ < SS;
        sq[s_][d] = ok ? base[s_ * 768 +       d] : 0.f;
        sk[s_][d] = ok ? base[s_ * 768 + 256 + d] : 0.f;
    }
    __syncthreads();
    // scores = q @ k^T * scale   (80x80x32 logical) — 16x16 threads, 5x5 each, unguarded
    const int ty = tid >> 4, tx = tid & 15;
    {
        const float scale = 0.17677669529663687f;   // 32^-0.5
        float a[5], bb[5], accs[5][5] = {};
        int r0 = ty * 5, c0 = tx * 5;
        for (int kk = 0; kk < HDIM; kk++) {
            #pragma unroll
            for (int i = 0; i < 5; i++) a[i]  = sq[r0 + i][kk];
            #pragma unroll
            for (int j = 0; j < 5; j++) bb[j] = sk[c0 + j][kk];
            #pragma unroll
            for (int i = 0; i < 5; i++)
                #pragma unroll
                for (int j = 0; j < 5; j++)
                    accs[i][j] += a[i] * bb[j];
        }
        #pragma unroll
        for (int i = 0; i < 5; i++)
            #pragma unroll
            for (int j = 0; j < 5; j++)
                sc[r0 + i][c0 + j] = accs[i][j] * scale;
    }
    __syncthreads();
    // reuse sq rows [0,72) for v
    for (int idx = tid; idx < SS * HDIM; idx += 256) {
        int s_ = idx >> 5, d = idx & 31;
        sq[s_][d] = base[s_ * 768 + 512 + d];
    }
    // top-20 threshold + softmax, one thread per row (register-only swap chain)
    if (tid < SS) {
        float top[TOPM];
        #pragma unroll
        for (int i = 0; i < TOPM; i++) top[i] = -INFINITY;
        for (int c = 0; c < SS; c++) {
            float val = sc[tid][c];
            if (val > top[TOPM-1]) {
                #pragma unroll
                for (int i = 0; i < TOPM; i++) {
                    float hi = fmaxf(top[i], val);
                    val      = fminf(top[i], val);
                    top[i]   = hi;
                }
            }
        }
        float thr = top[TOPM-1], mx = top[0];
        float sum = 0.f;
        for (int c = 0; c < SS; c++) {
            float v = sc[tid][c];
            float e = (v >= thr) ? __expf(v - mx) : 0.f;
            sc[tid][c] = e;
            sum += e;
        }
        float inv = 1.f / sum;
        for (int c = 0; c < SS; c++) sc[tid][c] *= inv;
    }
    __syncthreads();
    // out = p @ v  (72x32x72) — 16x16 threads, 5 rows x 2 cols each, unguarded reads
    {
        int r0 = ty * 5, c0 = tx * 2;
        float accs[5][2] = {};
        for (int kk = 0; kk < SS; kk++) {
            float v0 = sq[kk][c0], v1 = sq[kk][c0 + 1];
            #pragma unroll
            for (int i = 0; i < 5; i++) {
                float p = sc[r0 + i][kk];
                accs[i][0] += p * v0;
                accs[i][1] += p * v1;
            }
        }
        #pragma unroll
        for (int i = 0; i < 5; i++) {
            int r = r0 + i;
            if (r < SS) {
                float* o = out + (size_t)(b * SS + r) * DD + h * HDIM + c0;
                o[0] = accs[i][0];
                o[1] = accs[i][1];
            }
        }
    }
}

// ---------------- kernel 4: LayerNorm over D=256, warp per row ----------------
__global__ __launch_bounds__(256) void k_ln(const float* __restrict__ y,
                                            const float* __restrict__ g,
                                            const float* __restrict__ bt,
                                            float* __restrict__ x) {
    const int row  = blockIdx.x * 8 + (threadIdx.x >> 5);
    const int lane = threadIdx.x & 31;
    const float* yr = y + (size_t)row * DD + lane * 8;
    float4 v0 = *(const float4*)(yr);
    float4 v1 = *(const float4*)(yr + 4);
    float s = v0.x + v0.y + v0.z + v0.w + v1.x + v1.y + v1.z + v1.w;
    #pragma unroll
    for (int o = 16; o > 0; o >>= 1) s += __shfl_xor_sync(0xffffffffu, s, o);
    float mu = s * (1.f / DD);
    float d0x = v0.x - mu, d0y = v0.y - mu, d0z = v0.z - mu, d0w = v0.w - mu;
    float d1x = v1.x - mu, d1y = v1.y - mu, d1z = v1.z - mu, d1w = v1.w - mu;
    float s2 = d0x*d0x + d0y*d0y + d0z*d0z + d0w*d0w
             + d1x*d1x + d1y*d1y + d1z*d1z + d1w*d1w;
    #pragma unroll
    for (int o = 16; o > 0; o >>= 1) s2 += __shfl_xor_sync(0xffffffffu, s2, o);
    float rstd = rsqrtf(s2 * (1.f / DD) + LN_EPS);
    float4 g0 = *(const float4*)(g  + lane * 8);
    float4 g1 = *(const float4*)(g  + lane * 8 + 4);
    float4 b0 = *(const float4*)(bt + lane * 8);
    float4 b1 = *(const float4*)(bt + lane * 8 + 4);
    float4 o0, o1;
    o0.x = d0x * rstd * g0.x + b0.x; o0.y = d0y * rstd * g0.y + b0.y;
    o0.z = d0z * rstd * g0.z + b0.z; o0.w = d0w * rstd * g0.w + b0.w;
    o1.x = d1x * rstd * g1.x + b1.x; o1.y = d1y * rstd * g1.y + b1.y;
    o1.z = d1z * rstd * g1.z + b1.z; o1.w = d1w * rstd * g1.w + b1.w;
    float* xr = x + (size_t)row * DD + lane * 8;
    *(float4*)(xr)     = o0;
    *(float4*)(xr + 4) = o1;
}

// ---------------- kernel 5: fused seq-mean + classifier MLP ----------------
__global__ __launch_bounds__(128) void k_head(const float* __restrict__ x,
                                              const float* __restrict__ w1,
                                              const float* __restrict__ b1,
                                              const float* __restrict__ w2,
                                              const float* __restrict__ b2,
                                              float* __restrict__ out) {
    __shared__ float xm[DD];
    __shared__ float sh[4];
    const int b = blockIdx.x;
    const int tid = threadIdx.x;          // 128
    // mean over 72 tokens (two dims per thread)
    float a0 = 0.f, a1 = 0.f;
    const float* xb = x + (size_t)b * SS * DD;
    #pragma unroll 4
    for (int s = 0; s < SS; s++) {
        a0 += xb[s * DD + tid];
        a1 += xb[s * DD + tid + 128];
    }
    xm[tid]       = a0 * (1.f / SS);
    xm[tid + 128] = a1 * (1.f / SS);
    __syncthreads();
    float acc = b1[tid];
    #pragma unroll 8
    for (int k = 0; k < DD; k++)
        acc += xm[k] * w1[k * 128 + tid];
    float contrib = fmaxf(acc, 0.f) * w2[tid];
    const int lane = tid & 31, wid = tid >> 5;
    #pragma unroll
    for (int o = 16; o > 0; o >>= 1) contrib += __shfl_xor_sync(0xffffffffu, contrib, o);
    if (lane == 0) sh[wid] = contrib;
    __syncthreads();
    if (tid == 0)
        out[b] = sh[0] + sh[1] + sh[2] + sh[3] + b2[0];
}

// ---------------- launch ----------------
extern "C" void kernel_launch(void* const* d_in, const int* in_sizes, int n_in,
                              void* d_out, int out_size) {
    const float* feats  = (const float*)d_in[0];   // (1920,256,72)
    const float* pos    = (const float*)d_in[1];   // (1,72,256)
    const float* qkv_w  = (const float*)d_in[2];   // (2,256,768)
    const float* qkv_b  = (const float*)d_in[3];   // (2,768)
    const float* proj_w = (const float*)d_in[4];   // (2,256,256)
    const float* proj_b = (const float*)d_in[5];   // (2,256)
    const float* ln_g   = (const float*)d_in[6];   // (2,256)
    const float* ln_b   = (const float*)d_in[7];   // (2,256)
    const float* cls_w1 = (const float*)d_in[8];   // (256,128)
    const float* cls_b1 = (const float*)d_in[9];   // (128)
    const float* cls_w2 = (const float*)d_in[10];  // (128,1)
    const float* cls_b2 = (const float*)d_in[11];  // (1)
    float* out = (float*)d_out;                    // (32,60) -> 1920

    float *px, *pqkv, *patt, *ptmp;
    cudaGetSymbolAddress((void**)&px,    g_x);
    cudaGetSymbolAddress((void**)&pqkv,  g_qkv);
    cudaGetSymbolAddress((void**)&patt,  g_att);
    cudaGetSymbolAddress((void**)&ptmp,  g_tmp);

    // 1) x = transpose(features) + pos
    {
        dim3 grid(BNC, 3, 8), blk(32, 8);
        k_transpose<<<grid, blk>>>(feats, pos, px);
    }
    // 2) transformer layers
    for (int l = 0; l < NLAYERS; l++) {
        const float* qw = qkv_w  + (size_t)l * 256 * 768;
        const float* qb = qkv_b  + (size_t)l * 768;
        const float* pw = proj_w + (size_t)l * 256 * 256;
        const float* pb = proj_b + (size_t)l * 256;
        const float* lg = ln_g   + (size_t)l * 256;
        const float* lb = ln_b   + (size_t)l * 256;

        {   // qkv = x @ qw + qb
            dim3 grid(768 / 64, MTOT / 128);
            k_gemm_tf32x3<<<grid, 256>>>(px, qw, qb, nullptr, pqkv, 768);
        }
        {   // attention
            dim3 grid(BNC, NH);
            k_attn<<<grid, 256>>>(pqkv, patt);
        }
        {   // tmp = att @ pw + pb + x  (residual)
            dim3 grid(256 / 64, MTOT / 128);
            k_gemm_tf32x3<<<grid, 256>>>(patt, pw, pb, px, ptmp, 256);
        }
        // x = LN(tmp)
        k_ln<<<MTOT / 8, 256>>>(ptmp, lg, lb, px);
    }
    // 3) fused mean + classifier
    k_head<<<BNC, 128>>>(px, cls_w1, cls_b1, cls_w2, cls_b2, out);
}

// round 10
// speedup vs baseline: 1.2636x; 1.2636x over previous
#include <cuda_runtime.h>
#include <cuda_bf16.h>
#include <math.h>

// ---------------- problem constants ----------------
#define BATCH   32
#define NCLS    60
#define BNC     1920          // BATCH*NCLS
#define DD      256
#define SS      72
#define NH      8
#define HDIM    32
#define TOPM    20
#define NLAYERS 2
#define MTOT    (BNC*SS)      // 138240 rows
#define LN_EPS  1e-5f

// ---------------- scratch (device globals; no cudaMalloc allowed) ----------------
__device__ float g_x  [(size_t)MTOT*DD];        // activations fp32 (residual/mean)
__device__ float g_qkv[(size_t)MTOT*3*DD];      // qkv projections fp32
__device__ float g_tmp[(size_t)MTOT*DD];        // proj + residual (pre-LN)
__device__ __nv_bfloat16 g_xh[(size_t)MTOT*DD]; // x split hi (A of qkv gemm)
__device__ __nv_bfloat16 g_xl[(size_t)MTOT*DD]; // x split lo
__device__ __nv_bfloat16 g_ah[(size_t)MTOT*DD]; // attn-out split hi (A of proj gemm)
__device__ __nv_bfloat16 g_al[(size_t)MTOT*DD];
// transposed split weights: [N][K] layout, K=256
__device__ __nv_bfloat16 g_wqh[2*768*256], g_wql[2*768*256];
__device__ __nv_bfloat16 g_wph[2*256*256], g_wpl[2*256*256];

// ---------------- helpers ----------------
__device__ __forceinline__ void split_bf16(float v, __nv_bfloat16& h, __nv_bfloat16& l) {
    h = __float2bfloat16(v);
    l = __float2bfloat16(v - __bfloat162float(h));
}

__device__ __forceinline__ void mma_bf16(float* c, const unsigned* a, const unsigned* b) {
    asm volatile(
        "mma.sync.aligned.m16n8k16.row.col.f32.bf16.bf16.f32 "
        "{%0,%1,%2,%3}, {%4,%5,%6,%7}, {%8,%9}, {%0,%1,%2,%3};"
        : "+f"(c[0]), "+f"(c[1]), "+f"(c[2]), "+f"(c[3])
        : "r"(a[0]), "r"(a[1]), "r"(a[2]), "r"(a[3]),
          "r"(b[0]), "r"(b[1]));
}

__device__ __forceinline__ void cp_async16(void* smem, const void* gmem) {
    unsigned s = (unsigned)__cvta_generic_to_shared(smem);
    asm volatile("cp.async.cg.shared.global [%0], [%1], 16;\n" :: "r"(s), "l"(gmem));
}
__device__ __forceinline__ void cp_commit() { asm volatile("cp.async.commit_group;\n"); }
__device__ __forceinline__ void cp_wait1()  { asm volatile("cp.async.wait_group 1;\n"); }
__device__ __forceinline__ void cp_wait0()  { asm volatile("cp.async.wait_group 0;\n"); }

// ---------------- kernel 0: weight split + transpose  out[n][k] = split(w[k][n]) ------
__global__ void k_wsplitT(const float* __restrict__ w, __nv_bfloat16* __restrict__ oh,
                          __nv_bfloat16* __restrict__ ol, int K, int N) {
    int idx = blockIdx.x * 256 + threadIdx.x;
    if (idx >= K * N) return;
    int n = idx / K, k = idx - n * K;
    float v = w[(size_t)k * N + n];
    __nv_bfloat16 h, l;
    split_bf16(v, h, l);
    oh[idx] = h;
    ol[idx] = l;
}

// ---------------- kernel 1: transpose (BNC,D,S)->(BNC,S,D) + pos embed + split -------
__global__ __launch_bounds__(256) void k_transpose(const float* __restrict__ f,
                                                   const float* __restrict__ pos,
                                                   float* __restrict__ x,
                                                   __nv_bfloat16* __restrict__ xh,
                                                   __nv_bfloat16* __restrict__ xl) {
    __shared__ float t[32][33];
    int b  = blockIdx.x;
    int s0 = blockIdx.y * 32;
    int d0 = blockIdx.z * 32;
    int tx = threadIdx.x, ty = threadIdx.y;       // block (32,8)
    const float* fb = f + (size_t)b * DD * SS;
    #pragma unroll
    for (int i = 0; i < 4; i++) {
        int d = d0 + ty + i*8;
        int s = s0 + tx;
        t[ty + i*8][tx] = (s < SS) ? fb[d * SS + s] : 0.f;
    }
    __syncthreads();
    #pragma unroll
    for (int i = 0; i < 4; i++) {
        int s = s0 + ty + i*8;
        int d = d0 + tx;
        if (s < SS) {
            size_t o = (size_t)(b * SS + s) * DD + d;
            float v = t[tx][ty + i*8] + pos[s * DD + d];
            x[o] = v;
            __nv_bfloat16 h, l;
            split_bf16(v, h, l);
            xh[o] = h; xl[o] = l;
        }
    }
}

// ---------------- kernel 2: bf16x3 tensor-core GEMM, 2-stage cp.async pipeline -------
// C[M,N] = A[M,256] @ BT[N,256]^T + bias (+res), A/B pre-split bf16 hi/lo.
// Block tile 128x64, 8 warps (4m x 2n), warp 32x32 via m16n8k16 (3 mma per tile).
// Dynamic smem (u32 units): Ash@0, Asl@5120, Bsh@10240, Bsl@12800; row stride 20.
__global__ __launch_bounds__(256, 2) void k_gemm_bf16x3(
        const __nv_bfloat16* __restrict__ Ah, const __nv_bfloat16* __restrict__ Al,
        const __nv_bfloat16* __restrict__ BTh, const __nv_bfloat16* __restrict__ BTl,
        const float* __restrict__ bias, const float* __restrict__ res,
        float* __restrict__ C, int N) {
    extern __shared__ unsigned su[];
    const int tid  = threadIdx.x;
    const int m0   = blockIdx.y * 128;
    const int n0   = blockIdx.x * 64;
    const int warp = tid >> 5, lane = tid & 31;
    const int wm   = warp & 3;    // m offset 32*wm
    const int wn   = warp >> 2;   // n offset 32*wn
    const int g    = lane >> 2;   // 0..7
    const int t    = lane & 3;    // 0..3

    float acc[2][4][4];
    #pragma unroll
    for (int i = 0; i < 2; i++)
        #pragma unroll
        for (int j = 0; j < 4; j++)
            #pragma unroll
            for (int r = 0; r < 4; r++) acc[i][j][r] = 0.f;

    // stage loader: A 128x32 bf16 hi+lo (2+2 chunks/thread), B 64x32 hi+lo (1+1)
    auto load_stage = [&](int st, int k0) {
        #pragma unroll
        for (int i = 0; i < 2; i++) {
            int idx = tid + i * 256;
            int m = idx >> 2, c = idx & 3;
            size_t go = (size_t)(m0 + m) * 256 + k0 + c * 8;
            cp_async16(&su[st * 2560 + m * 20 + c * 4],        Ah + go);
            cp_async16(&su[5120 + st * 2560 + m * 20 + c * 4], Al + go);
        }
        {
            int n = tid >> 2, c = tid & 3;
            size_t go = (size_t)(n0 + n) * 256 + k0 + c * 8;
            cp_async16(&su[10240 + st * 1280 + n * 20 + c * 4], BTh + go);
            cp_async16(&su[12800 + st * 1280 + n * 20 + c * 4], BTl + go);
        }
        cp_commit();
    };

    load_stage(0, 0);
    #pragma unroll
    for (int kc = 0; kc < 8; kc++) {
        const int st = kc & 1;
        if (kc < 7) load_stage(st ^ 1, (kc + 1) * 32);
        if (kc < 7) cp_wait1(); else cp_wait0();
        __syncthreads();
        #pragma unroll
        for (int ks = 0; ks < 2; ks++) {          // two k16 steps per 32-K stage
            const int kcol = ks * 8;
            unsigned ah[2][4], al[2][4], bh[4][2], bl[4][2];
            #pragma unroll
            for (int mt = 0; mt < 2; mt++) {
                int base = st * 2560 + (wm * 32 + mt * 16 + g) * 20 + kcol;
                ah[mt][0] = su[base + t];
                ah[mt][1] = su[base + 160 + t];       // +8 rows * 20
                ah[mt][2] = su[base + t + 4];
                ah[mt][3] = su[base + 160 + t + 4];
                al[mt][0] = su[5120 + base + t];
                al[mt][1] = su[5120 + base + 160 + t];
                al[mt][2] = su[5120 + base + t + 4];
                al[mt][3] = su[5120 + base + 160 + t + 4];
            }
            #pragma unroll
            for (int nt = 0; nt < 4; nt++) {
                int base = 10240 + st * 1280 + (wn * 32 + nt * 8 + g) * 20 + kcol;
                bh[nt][0] = su[base + t];
                bh[nt][1] = su[base + t + 4];
                bl[nt][0] = su[2560 + base + t];
                bl[nt][1] = su[2560 + base + t + 4];
            }
            #pragma unroll
            for (int mt = 0; mt < 2; mt++)
                #pragma unroll
                for (int nt = 0; nt < 4; nt++) {
                    mma_bf16(acc[mt][nt], ah[mt], bl[nt]);   // cross terms first
                    mma_bf16(acc[mt][nt], al[mt], bh[nt]);
                    mma_bf16(acc[mt][nt], ah[mt], bh[nt]);   // dominant term
                }
        }
        __syncthreads();
    }
    // epilogue: bias (+residual), float2 stores
    #pragma unroll
    for (int mt = 0; mt < 2; mt++) {
        #pragma unroll
        for (int nt = 0; nt < 4; nt++) {
            int m = m0 + wm * 32 + mt * 16 + g;
            int n = n0 + wn * 32 + nt * 8 + 2 * t;
            float bx = bias[n], by = bias[n + 1];
            float2 o0 = make_float2(acc[mt][nt][0] + bx, acc[mt][nt][1] + by);
            float2 o1 = make_float2(acc[mt][nt][2] + bx, acc[mt][nt][3] + by);
            if (res) {
                float2 r0 = *(const float2*)(res + (size_t)m * N + n);
                float2 r1 = *(const float2*)(res + (size_t)(m + 8) * N + n);
                o0.x += r0.x; o0.y += r0.y;
                o1.x += r1.x; o1.y += r1.y;
            }
            *(float2*)(C + (size_t)m * N + n)       = o0;
            *(float2*)(C + (size_t)(m + 8) * N + n) = o1;
        }
    }
}

// ---------------- kernel 3: top-M attention per (batch, head), split bf16 output -----
__global__ __launch_bounds__(256) void k_attn(const float* __restrict__ qkv,
                                              __nv_bfloat16* __restrict__ oh,
                                              __nv_bfloat16* __restrict__ ol) {
    __shared__ float sq[80][33];   // q, later reused for v (rows 72..79 stay zero)
    __shared__ float sk[80][33];
    __shared__ float sc[80][81];   // scores -> probs
    const int b = blockIdx.x;
    const int h = blockIdx.y;
    const int tid = threadIdx.x;
    const float* base = qkv + (size_t)b * SS * 768 + h * HDIM;
    for (int idx = tid; idx < 80 * HDIM; idx += 256) {
        int s_ = idx >> 5, d = idx & 31;
        bool ok = s_ < SS;
        sq[s_][d] = ok ? base[s_ * 768 +       d] : 0.f;
        sk[s_][d] = ok ? base[s_ * 768 + 256 + d] : 0.f;
    }
    __syncthreads();
    const int ty = tid >> 4, tx = tid & 15;
    {
        const float scale = 0.17677669529663687f;   // 32^-0.5
        float a[5], bb[5], accs[5][5] = {};
        int r0 = ty * 5, c0 = tx * 5;
        for (int kk = 0; kk < HDIM; kk++) {
            #pragma unroll
            for (int i = 0; i < 5; i++) a[i]  = sq[r0 + i][kk];
            #pragma unroll
            for (int j = 0; j < 5; j++) bb[j] = sk[c0 + j][kk];
            #pragma unroll
            for (int i = 0; i < 5; i++)
                #pragma unroll
                for (int j = 0; j < 5; j++)
                    accs[i][j] += a[i] * bb[j];
        }
        #pragma unroll
        for (int i = 0; i < 5; i++)
            #pragma unroll
            for (int j = 0; j < 5; j++)
                sc[r0 + i][c0 + j] = accs[i][j] * scale;
    }
    __syncthreads();
    for (int idx = tid; idx < SS * HDIM; idx += 256) {
        int s_ = idx >> 5, d = idx & 31;
        sq[s_][d] = base[s_ * 768 + 512 + d];
    }
    if (tid < SS) {
        float top[TOPM];
        #pragma unroll
        for (int i = 0; i < TOPM; i++) top[i] = -INFINITY;
        for (int c = 0; c < SS; c++) {
            float val = sc[tid][c];
            if (val > top[TOPM-1]) {
                #pragma unroll
                for (int i = 0; i < TOPM; i++) {
                    float hi = fmaxf(top[i], val);
                    val      = fminf(top[i], val);
                    top[i]   = hi;
                }
            }
        }
        float thr = top[TOPM-1], mx = top[0];
        float sum = 0.f;
        for (int c = 0; c < SS; c++) {
            float v = sc[tid][c];
            float e = (v >= thr) ? __expf(v - mx) : 0.f;
            sc[tid][c] = e;
            sum += e;
        }
        float inv = 1.f / sum;
        for (int c = 0; c < SS; c++) sc[tid][c] *= inv;
    }
    __syncthreads();
    {
        int r0 = ty * 5, c0 = tx * 2;
        float accs[5][2] = {};
        for (int kk = 0; kk < SS; kk++) {
            float v0 = sq[kk][c0], v1 = sq[kk][c0 + 1];
            #pragma unroll
            for (int i = 0; i < 5; i++) {
                float p = sc[r0 + i][kk];
                accs[i][0] += p * v0;
                accs[i][1] += p * v1;
            }
        }
        #pragma unroll
        for (int i = 0; i < 5; i++) {
            int r = r0 + i;
            if (r < SS) {
                size_t o = (size_t)(b * SS + r) * DD + h * HDIM + c0;
                __nv_bfloat16 h0, l0, h1, l1;
                split_bf16(accs[i][0], h0, l0);
                split_bf16(accs[i][1], h1, l1);
                oh[o] = h0; oh[o + 1] = h1;
                ol[o] = l0; ol[o + 1] = l1;
            }
        }
    }
}

// ---------------- kernel 4: LayerNorm over D=256, warp per row, split outputs --------
__global__ __launch_bounds__(256) void k_ln(const float* __restrict__ y,
                                            const float* __restrict__ g,
                                            const float* __restrict__ bt,
                                            float* __restrict__ x,
                                            __nv_bfloat16* __restrict__ xh,
                                            __nv_bfloat16* __restrict__ xl) {
    const int row  = blockIdx.x * 8 + (threadIdx.x >> 5);
    const int lane = threadIdx.x & 31;
    const float* yr = y + (size_t)row * DD + lane * 8;
    float4 v0 = *(const float4*)(yr);
    float4 v1 = *(const float4*)(yr + 4);
    float s = v0.x + v0.y + v0.z + v0.w + v1.x + v1.y + v1.z + v1.w;
    #pragma unroll
    for (int o = 16; o > 0; o >>= 1) s += __shfl_xor_sync(0xffffffffu, s, o);
    float mu = s * (1.f / DD);
    float d0x = v0.x - mu, d0y = v0.y - mu, d0z = v0.z - mu, d0w = v0.w - mu;
    float d1x = v1.x - mu, d1y = v1.y - mu, d1z = v1.z - mu, d1w = v1.w - mu;
    float s2 = d0x*d0x + d0y*d0y + d0z*d0z + d0w*d0w
             + d1x*d1x + d1y*d1y + d1z*d1z + d1w*d1w;
    #pragma unroll
    for (int o = 16; o > 0; o >>= 1) s2 += __shfl_xor_sync(0xffffffffu, s2, o);
    float rstd = rsqrtf(s2 * (1.f / DD) + LN_EPS);
    float4 g0 = *(const float4*)(g  + lane * 8);
    float4 g1 = *(const float4*)(g  + lane * 8 + 4);
    float4 b0 = *(const float4*)(bt + lane * 8);
    float4 b1 = *(const float4*)(bt + lane * 8 + 4);
    float o0[8];
    o0[0] = d0x * rstd * g0.x + b0.x; o0[1] = d0y * rstd * g0.y + b0.y;
    o0[2] = d0z * rstd * g0.z + b0.z; o0[3] = d0w * rstd * g0.w + b0.w;
    o0[4] = d1x * rstd * g1.x + b1.x; o0[5] = d1y * rstd * g1.y + b1.y;
    o0[6] = d1z * rstd * g1.z + b1.z; o0[7] = d1w * rstd * g1.w + b1.w;
    size_t ro = (size_t)row * DD + lane * 8;
    *(float4*)(x + ro)     = make_float4(o0[0], o0[1], o0[2], o0[3]);
    *(float4*)(x + ro + 4) = make_float4(o0[4], o0[5], o0[6], o0[7]);
    __nv_bfloat16 hh[8], ll[8];
    #pragma unroll
    for (int i = 0; i < 8; i++) split_bf16(o0[i], hh[i], ll[i]);
    *(uint4*)(xh + ro) = *(uint4*)hh;   // 8 bf16 = 16B
    *(uint4*)(xl + ro) = *(uint4*)ll;
}

// ---------------- kernel 5: fused seq-mean + classifier MLP ----------------
__global__ __launch_bounds__(128) void k_head(const float* __restrict__ x,
                                              const float* __restrict__ w1,
                                              const float* __restrict__ b1,
                                              const float* __restrict__ w2,
                                              const float* __restrict__ b2,
                                              float* __restrict__ out) {
    __shared__ float xm[DD];
    __shared__ float sh[4];
    const int b = blockIdx.x;
    const int tid = threadIdx.x;          // 128
    float a0 = 0.f, a1 = 0.f;
    const float* xb = x + (size_t)b * SS * DD;
    #pragma unroll 4
    for (int s = 0; s < SS; s++) {
        a0 += xb[s * DD + tid];
        a1 += xb[s * DD + tid + 128];
    }
    xm[tid]       = a0 * (1.f / SS);
    xm[tid + 128] = a1 * (1.f / SS);
    __syncthreads();
    float acc = b1[tid];
    #pragma unroll 8
    for (int k = 0; k < DD; k++)
        acc += xm[k] * w1[k * 128 + tid];
    float contrib = fmaxf(acc, 0.f) * w2[tid];
    const int lane = tid & 31, wid = tid >> 5;
    #pragma unroll
    for (int o = 16; o > 0; o >>= 1) contrib += __shfl_xor_sync(0xffffffffu, contrib, o);
    if (lane == 0) sh[wid] = contrib;
    __syncthreads();
    if (tid == 0)
        out[b] = sh[0] + sh[1] + sh[2] + sh[3] + b2[0];
}

// ---------------- launch ----------------
extern "C" void kernel_launch(void* const* d_in, const int* in_sizes, int n_in,
                              void* d_out, int out_size) {
    const float* feats  = (const float*)d_in[0];   // (1920,256,72)
    const float* pos    = (const float*)d_in[1];   // (1,72,256)
    const float* qkv_w  = (const float*)d_in[2];   // (2,256,768)
    const float* qkv_b  = (const float*)d_in[3];   // (2,768)
    const float* proj_w = (const float*)d_in[4];   // (2,256,256)
    const float* proj_b = (const float*)d_in[5];   // (2,256)
    const float* ln_g   = (const float*)d_in[6];   // (2,256)
    const float* ln_b   = (const float*)d_in[7];   // (2,256)
    const float* cls_w1 = (const float*)d_in[8];   // (256,128)
    const float* cls_b1 = (const float*)d_in[9];   // (128)
    const float* cls_w2 = (const float*)d_in[10];  // (128,1)
    const float* cls_b2 = (const float*)d_in[11];  // (1)
    float* out = (float*)d_out;                    // (32,60) -> 1920

    float *px, *pqkv, *ptmp;
    __nv_bfloat16 *pxh, *pxl, *pah, *pal, *pwqh, *pwql, *pwph, *pwpl;
    cudaGetSymbolAddress((void**)&px,   g_x);
    cudaGetSymbolAddress((void**)&pqkv, g_qkv);
    cudaGetSymbolAddress((void**)&ptmp, g_tmp);
    cudaGetSymbolAddress((void**)&pxh,  g_xh);
    cudaGetSymbolAddress((void**)&pxl,  g_xl);
    cudaGetSymbolAddress((void**)&pah,  g_ah);
    cudaGetSymbolAddress((void**)&pal,  g_al);
    cudaGetSymbolAddress((void**)&pwqh, g_wqh);
    cudaGetSymbolAddress((void**)&pwql, g_wql);
    cudaGetSymbolAddress((void**)&pwph, g_wph);
    cudaGetSymbolAddress((void**)&pwpl, g_wpl);

    // idempotent, graph-capture-safe (not a stream op, not an allocation)
    cudaFuncSetAttribute(k_gemm_bf16x3,
                         cudaFuncAttributeMaxDynamicSharedMemorySize, 61440);

    // 0) weight split+transpose (per layer)
    for (int l = 0; l < NLAYERS; l++) {
        k_wsplitT<<<(768*256 + 255)/256, 256>>>(qkv_w + (size_t)l*256*768,
                                                pwqh + (size_t)l*768*256,
                                                pwql + (size_t)l*768*256, 256, 768);
        k_wsplitT<<<(256*256 + 255)/256, 256>>>(proj_w + (size_t)l*256*256,
                                                pwph + (size_t)l*256*256,
                                                pwpl + (size_t)l*256*256, 256, 256);
    }
    // 1) x = transpose(features) + pos (fp32 + split)
    {
        dim3 grid(BNC, 3, 8), blk(32, 8);
        k_transpose<<<grid, blk>>>(feats, pos, px, pxh, pxl);
    }
    // 2) transformer layers
    for (int l = 0; l < NLAYERS; l++) {
        const float* qb = qkv_b  + (size_t)l * 768;
        const float* pb = proj_b + (size_t)l * 256;
        const float* lg = ln_g   + (size_t)l * 256;
        const float* lb = ln_b   + (size_t)l * 256;
        const __nv_bfloat16* wqh = pwqh + (size_t)l * 768 * 256;
        const __nv_bfloat16* wql = pwql + (size_t)l * 768 * 256;
        const __nv_bfloat16* wph = pwph + (size_t)l * 256 * 256;
        const __nv_bfloat16* wpl = pwpl + (size_t)l * 256 * 256;

        {   // qkv = x @ qw + qb
            dim3 grid(768 / 64, MTOT / 128);
            k_gemm_bf16x3<<<grid, 256, 61440>>>(pxh, pxl, wqh, wql, qb, nullptr, pqkv, 768);
        }
        {   // attention -> split bf16 output
            dim3 grid(BNC, NH);
            k_attn<<<grid, 256>>>(pqkv, pah, pal);
        }
        {   // tmp = att @ pw + pb + x  (residual)
            dim3 grid(256 / 64, MTOT / 128);
            k_gemm_bf16x3<<<grid, 256, 61440>>>(pah, pal, wph, wpl, pb, px, ptmp, 256);
        }
        // x = LN(tmp) (fp32 + split)
        k_ln<<<MTOT / 8, 256>>>(ptmp, lg, lb, px, pxh, pxl);
    }
    // 3) fused mean + classifier
    k_head<<<BNC, 128>>>(px, cls_w1, cls_b1, cls_w2, cls_b2, out);
}